// round 9
// baseline (speedup 1.0000x reference)
#include <cuda_runtime.h>
#include <cuda_bf16.h>
#include <cstdint>

// Problem dims (fixed by dataset): N=20000, E=320000, B=16,
// node_dim=256, cond_dim=512, out_dim=256.
#define NMAX 20000
#define EMAX 320000
#define BMAX 16

// Scratch (allocation-free rule: __device__ globals)
__device__ __align__(16) float g_x[(size_t)NMAX * 256];
__device__ __align__(16) float g_gamma[BMAX * 256];
__device__ __align__(16) float g_beta[BMAX * 256];
__device__ __align__(16) __nv_bfloat16 g_Wh[256 * 256];  // W^T hi, [n][k]
__device__ __align__(16) __nv_bfloat16 g_Wl[256 * 256];  // W^T lo, [n][k]
__device__ int   g_cnt[NMAX];
__device__ int   g_off[NMAX + 1];
__device__ int   g_cur[NMAX];
__device__ int   g_blk[128];
__device__ int   g_src[EMAX];
__device__ float g_wgt[EMAX];

#define SMEM_SWIZZLE_128B(off) ((off) ^ (((off) >> 3) & 0x70))

// warp-level bf16 MMA (baseline PTX, works on compute_103 targets)
__device__ __forceinline__ void mma16816(float* c, const uint32_t* a,
                                         const uint32_t* b) {
    asm volatile(
        "mma.sync.aligned.m16n8k16.row.col.f32.bf16.bf16.f32 "
        "{%0,%1,%2,%3},{%4,%5,%6,%7},{%8,%9},{%0,%1,%2,%3};"
        : "+f"(c[0]), "+f"(c[1]), "+f"(c[2]), "+f"(c[3])
        : "r"(a[0]), "r"(a[1]), "r"(a[2]), "r"(a[3]), "r"(b[0]), "r"(b[1]));
}
__device__ __forceinline__ void ldsm_x4(uint32_t* r, uint32_t addr) {
    asm volatile("ldmatrix.sync.aligned.m8n8.x4.shared.b16 {%0,%1,%2,%3}, [%4];"
                 : "=r"(r[0]), "=r"(r[1]), "=r"(r[2]), "=r"(r[3]) : "r"(addr));
}
__device__ __forceinline__ uint32_t smem_to_u32(const void* p) {
    uint32_t a;
    asm("{ .reg .u64 t; cvta.to.shared.u64 t, %1; cvt.u32.u64 %0, t; }"
        : "=r"(a) : "l"(p));
    return a;
}
#define CP_ASYNC16(dst, src) \
    asm volatile("cp.async.cg.shared.global [%0], [%1], 16;" \
                 :: "r"(dst), "l"(src) : "memory")
#define CP_COMMIT() asm volatile("cp.async.commit_group;" ::: "memory")
#define CP_WAIT1() asm volatile("cp.async.wait_group 1;" ::: "memory")
#define CP_WAIT0() asm volatile("cp.async.wait_group 0;" ::: "memory")

// ---------------------------------------------------------------------------
// 0. W prep: split-transpose W[k][n] fp32 -> g_Wh/g_Wl[n][k] bf16.
// ---------------------------------------------------------------------------
__global__ void wprep_kernel(const float* __restrict__ W) {
    __shared__ float t[32][33];
    int bi = blockIdx.x;           // n-tile
    int bj = blockIdx.y;           // k-tile
    int tx = threadIdx.x, ty = threadIdx.y;   // 32 x 8
#pragma unroll
    for (int i = 0; i < 4; i++)
        t[ty + i * 8][tx] = W[(size_t)(bj * 32 + ty + i * 8) * 256 + bi * 32 + tx];
    __syncthreads();
#pragma unroll
    for (int i = 0; i < 4; i++) {
        int n = bi * 32 + ty + i * 8;
        int k = bj * 32 + tx;
        float v = t[tx][ty + i * 8];
        __nv_bfloat16 h = __float2bfloat16_rn(v);
        __nv_bfloat16 l = __float2bfloat16_rn(v - __bfloat162float(h));
        g_Wh[(size_t)n * 256 + k] = h;
        g_Wl[(size_t)n * 256 + k] = l;
    }
}

// ---------------------------------------------------------------------------
// 1. FiLM params + zero CSR counters.
// ---------------------------------------------------------------------------
__global__ void film_zero_kernel(const float* __restrict__ cond,
                                 const float* __restrict__ Wc,
                                 const float* __restrict__ bc, int B, int N) {
    int tid = blockIdx.x * blockDim.x + threadIdx.x;
    for (int i = tid; i < N; i += gridDim.x * blockDim.x) {
        g_cnt[i] = 0; g_cur[i] = 0;
    }
    if (tid >= B * 512) return;
    int b = tid >> 9;
    int o = tid & 511;
    const float* c = cond + b * 512;
    float acc = bc[o];
#pragma unroll 4
    for (int k = 0; k < 512; k++) acc = fmaf(c[k], Wc[k * 512 + o], acc);
    if (o < 256) g_gamma[b * 256 + o] = acc + 1.0f;
    else         g_beta[b * 256 + (o - 256)] = acc;
}

// ---------------------------------------------------------------------------
// 2. hist
// ---------------------------------------------------------------------------
__global__ void hist_kernel(const int* __restrict__ ni, int E) {
    int e = blockIdx.x * blockDim.x + threadIdx.x;
    if (e < E) atomicAdd(&g_cnt[ni[e]], 1);
}

// ---------------------------------------------------------------------------
// 3. Tensor GEMM (mma.sync bf16 3-term split) + LN + FiLM + ReLU.
//    512 threads = 16 warps (2m x 8n), warp tile 32x32 -> 32 acc regs/thread.
//    __launch_bounds__(512,2) -> 32 warps/SM for latency hiding.
// ---------------------------------------------------------------------------
#define SM_W0 0
#define SM_W1 32768
#define SM_AH 65536
#define SM_AL 69632
#define SM_ST 73728
#define SM_TOTAL (73728 + 512)

__device__ __forceinline__ void issue_w_chunk512(uint32_t wbuf, int kt, int tid) {
#pragma unroll
    for (int it = 0; it < 2; it++) {
        int item = it * 512 + tid;
        int n = item >> 2;
        int c = item & 3;
        uint32_t off = (uint32_t)((n & 127) * 128 + (n >> 7) * 64 + c * 16);
        uint32_t sw = SMEM_SWIZZLE_128B(off);
        size_t go = (size_t)n * 512 + (size_t)kt * 64 + c * 16;   // bytes
        CP_ASYNC16(wbuf + sw, (const char*)g_Wh + go);
        CP_ASYNC16(wbuf + 16384 + sw, (const char*)g_Wl + go);
    }
    CP_COMMIT();
}

__global__ void __launch_bounds__(512, 2)
gemm_ln_kernel(const float* __restrict__ A,
               const int* __restrict__ batch_ids, int N) {
    extern __shared__ char sm[];
    uint32_t smb = smem_to_u32(sm);
    float* s_sum = (float*)(sm + SM_ST);        // [64]
    float* s_sq  = (float*)(sm + SM_ST + 256);  // [64]

    int tid = threadIdx.x;
    int wid = tid >> 5, lane = tid & 31;
    int mw = wid >> 3;           // 0..1  m-warp
    int nw = wid & 7;            // 0..7  n-warp (32 cols each)
    int m0 = blockIdx.x * 64;

    if (tid < 128) ((float*)(sm + SM_ST))[tid] = 0.0f;

    // ldmatrix per-lane addressing
    int g = lane >> 3;
    int lr = lane & 7;
    uint32_t axor = (uint32_t)(lr << 4);
    // A: packed layout byte(m,krel) = (m&31)*128 + (m>>5)*64 + krel*2
    uint32_t a_row[2];
#pragma unroll
    for (int tm = 0; tm < 2; tm++)
        a_row[tm] = (uint32_t)((tm * 16 + (g & 1) * 8 + lr) * 128);
    uint32_t a_low_base = (uint32_t)(mw * 64 + (g >> 1) * 16);
    // B: packed layout byte(n,krel) = (n&127)*128 + (n>>7)*64 + krel*2
    // warp covers n = nw*32 .. +31; two x4 loads (16 n each)
    uint32_t b_row[2];
#pragma unroll
    for (int np = 0; np < 2; np++)
        b_row[np] = (uint32_t)(((nw & 3) * 32 + np * 16 + ((g >> 1) & 1) * 8 + lr) * 128);
    uint32_t b_low_base = (uint32_t)((nw >> 2) * 64 + (g & 1) * 16);

    // A prefetch mapping: 512 threads, 64 rows x 32 floats per chunk
    int pm = tid >> 3;                 // 0..63 row
    int prow = m0 + pm;
    const float* aptr = A + (size_t)prow * 256 + (tid & 7) * 4;
    bool pvalid = (prow < N);
    uint32_t a_st_off = SMEM_SWIZZLE_128B(
        (uint32_t)((pm & 31) * 128 + (pm >> 5) * 64 + (tid & 7) * 8));

    float c[2][4][4];
#pragma unroll
    for (int i = 0; i < 2; i++)
#pragma unroll
        for (int j = 0; j < 4; j++)
#pragma unroll
            for (int q = 0; q < 4; q++) c[i][j][q] = 0.0f;

    // ---- prologue
    issue_w_chunk512(smb + SM_W0, 0, tid);
    issue_w_chunk512(smb + SM_W1, 1, tid);
    float4 aP = make_float4(0.f, 0.f, 0.f, 0.f);
    if (pvalid) aP = *(const float4*)(aptr);

    for (int kt = 0; kt < 8; kt++) {
        if (kt > 0) __syncthreads();
        if (kt >= 1 && kt + 1 < 8)
            issue_w_chunk512(smb + SM_W0 + ((kt + 1) & 1) * 32768, kt + 1, tid);

        // store converted A(kt): 4 floats -> 2 hi u32 + 2 lo u32
        {
            float f[4] = {aP.x, aP.y, aP.z, aP.w};
            uint32_t h[2], l[2];
#pragma unroll
            for (int q = 0; q < 2; q++) {
                __nv_bfloat16 h0 = __float2bfloat16_rn(f[2 * q]);
                __nv_bfloat16 h1 = __float2bfloat16_rn(f[2 * q + 1]);
                __nv_bfloat16 l0 = __float2bfloat16_rn(f[2 * q] - __bfloat162float(h0));
                __nv_bfloat16 l1 = __float2bfloat16_rn(f[2 * q + 1] - __bfloat162float(h1));
                h[q] = ((uint32_t)__bfloat16_as_ushort(h1) << 16) | __bfloat16_as_ushort(h0);
                l[q] = ((uint32_t)__bfloat16_as_ushort(l1) << 16) | __bfloat16_as_ushort(l0);
            }
            *(uint2*)(sm + SM_AH + a_st_off) = make_uint2(h[0], h[1]);
            *(uint2*)(sm + SM_AL + a_st_off) = make_uint2(l[0], l[1]);
        }

        if (kt == 7) { CP_WAIT0(); } else { CP_WAIT1(); }
        __syncthreads();

        if (kt + 1 < 8 && pvalid)
            aP = *(const float4*)(aptr + (kt + 1) * 32);

        uint32_t wb = smb + SM_W0 + (kt & 1) * 32768;
#pragma unroll
        for (int ks = 0; ks < 2; ks++) {
            uint32_t alow = (a_low_base + (uint32_t)(ks * 32)) ^ axor;
            uint32_t blow = (b_low_base + (uint32_t)(ks * 32)) ^ axor;
            uint32_t ah0[4], ah1[4];
            ldsm_x4(ah0, smb + SM_AH + a_row[0] + alow);
            ldsm_x4(ah1, smb + SM_AH + a_row[1] + alow);
            uint32_t bf[2][4];
            ldsm_x4(bf[0], wb + b_row[0] + blow);
            ldsm_x4(bf[1], wb + b_row[1] + blow);

            // pass 1: ah * bh  (8 independent accumulators)
#pragma unroll
            for (int np = 0; np < 2; np++)
#pragma unroll
                for (int sb = 0; sb < 2; sb++) {
                    mma16816(c[0][np * 2 + sb], ah0, bf[np] + 2 * sb);
                    mma16816(c[1][np * 2 + sb], ah1, bf[np] + 2 * sb);
                }
            // pass 2: al * bh
            {
                uint32_t al0[4], al1[4];
                ldsm_x4(al0, smb + SM_AL + a_row[0] + alow);
                ldsm_x4(al1, smb + SM_AL + a_row[1] + alow);
#pragma unroll
                for (int np = 0; np < 2; np++)
#pragma unroll
                    for (int sb = 0; sb < 2; sb++) {
                        mma16816(c[0][np * 2 + sb], al0, bf[np] + 2 * sb);
                        mma16816(c[1][np * 2 + sb], al1, bf[np] + 2 * sb);
                    }
            }
            // pass 3: ah * bl (reload B frags with lo-part)
            ldsm_x4(bf[0], wb + 16384 + b_row[0] + blow);
            ldsm_x4(bf[1], wb + 16384 + b_row[1] + blow);
#pragma unroll
            for (int np = 0; np < 2; np++)
#pragma unroll
                for (int sb = 0; sb < 2; sb++) {
                    mma16816(c[0][np * 2 + sb], ah0, bf[np] + 2 * sb);
                    mma16816(c[1][np * 2 + sb], ah1, bf[np] + 2 * sb);
                }
        }
    }

    // ---- LN stats: quad-shuffle partials, smem atomics across 8 n-warps ----
#pragma unroll
    for (int tm = 0; tm < 2; tm++) {
#pragma unroll
        for (int h = 0; h < 2; h++) {
            int rl = mw * 32 + tm * 16 + h * 8 + (lane >> 2);
            float ps = 0.f, pq = 0.f;
#pragma unroll
            for (int nt = 0; nt < 4; nt++) {
                float v0 = c[tm][nt][2 * h], v1 = c[tm][nt][2 * h + 1];
                ps += v0 + v1;
                pq = fmaf(v0, v0, fmaf(v1, v1, pq));
            }
            ps += __shfl_xor_sync(0xffffffffu, ps, 1);
            pq += __shfl_xor_sync(0xffffffffu, pq, 1);
            ps += __shfl_xor_sync(0xffffffffu, ps, 2);
            pq += __shfl_xor_sync(0xffffffffu, pq, 2);
            if ((lane & 3) == 0) {
                atomicAdd(&s_sum[rl], ps);
                atomicAdd(&s_sq[rl], pq);
            }
        }
    }
    __syncthreads();

    // ---- normalize + FiLM + ReLU from fragments -> g_x ----
#pragma unroll
    for (int tm = 0; tm < 2; tm++) {
#pragma unroll
        for (int h = 0; h < 2; h++) {
            int rl = mw * 32 + tm * 16 + h * 8 + (lane >> 2);
            int row = m0 + rl;
            if (row >= N) continue;
            float mu = s_sum[rl] * (1.0f / 256.0f);
            float var = fmaxf(s_sq[rl] * (1.0f / 256.0f) - mu * mu, 0.0f);
            float rs = rsqrtf(var + 1e-5f);
            int b = batch_ids[row];
            const float* gg = g_gamma + b * 256;
            const float* bb = g_beta + b * 256;
            float* xo = g_x + (size_t)row * 256;
#pragma unroll
            for (int nt = 0; nt < 4; nt++) {
                int col = nw * 32 + nt * 8 + (lane & 3) * 2;
                float2 gv = *(const float2*)(gg + col);
                float2 ev = *(const float2*)(bb + col);
                float2 o;
                o.x = fmaxf(fmaf((c[tm][nt][2 * h] - mu) * rs, gv.x, ev.x), 0.f);
                o.y = fmaxf(fmaf((c[tm][nt][2 * h + 1] - mu) * rs, gv.y, ev.y), 0.f);
                *(float2*)(xo + col) = o;
            }
        }
    }
}

// ---------------------------------------------------------------------------
// scan_part / scan_add / fill / agg (unchanged)
// ---------------------------------------------------------------------------
__global__ void scan_part_kernel(int N) {
    __shared__ int wsum[8];
    int idx = blockIdx.x * 256 + threadIdx.x;
    int lane = threadIdx.x & 31;
    int wid = threadIdx.x >> 5;
    int v = (idx < N) ? g_cnt[idx] : 0;
    int s = v;
#pragma unroll
    for (int o = 1; o < 32; o <<= 1) {
        int t = __shfl_up_sync(0xffffffffu, s, o);
        if (lane >= o) s += t;
    }
    if (lane == 31) wsum[wid] = s;
    __syncthreads();
    if (wid == 0) {
        int ws = (lane < 8) ? wsum[lane] : 0;
#pragma unroll
        for (int o = 1; o < 8; o <<= 1) {
            int t = __shfl_up_sync(0xffffffffu, ws, o);
            if (lane >= o) ws += t;
        }
        if (lane < 8) wsum[lane] = ws;
    }
    __syncthreads();
    int excl = s - v + (wid ? wsum[wid - 1] : 0);
    if (idx < N) g_off[idx] = excl;
    if (threadIdx.x == 255) g_blk[blockIdx.x] = excl + v;
}

__global__ void scan_add_kernel(int N, int E, int nblk) {
    __shared__ int prefix;
    int bid = blockIdx.x;
    if (threadIdx.x < 32) {
        int acc = 0;
        for (int t = threadIdx.x; t < bid; t += 32) acc += g_blk[t];
#pragma unroll
        for (int o = 16; o; o >>= 1) acc += __shfl_xor_sync(0xffffffffu, acc, o);
        if (threadIdx.x == 0) prefix = acc;
    }
    __syncthreads();
    int idx = bid * 256 + threadIdx.x;
    if (idx < N && bid > 0) g_off[idx] += prefix;
    if (idx == 0) g_off[N] = E;
}

__global__ void fill_kernel(const int* __restrict__ ni,
                            const int* __restrict__ nj,
                            const float* __restrict__ ew,
                            const float* __restrict__ ep, int E) {
    int e = blockIdx.x * blockDim.x + threadIdx.x;
    if (e < E) {
        int dst = ni[e];
        int p = atomicAdd(&g_cur[dst], 1);
        int pos = g_off[dst] + p;
        g_src[pos] = nj[e];
        g_wgt[pos] = ew[e] * ep[e];
    }
}

__global__ void agg_kernel(float* __restrict__ out, int N) {
    int gw = (blockIdx.x * blockDim.x + threadIdx.x) >> 5;
    int lane = threadIdx.x & 31;
    if (gw >= N) return;
    int s = g_off[gw];
    int e = g_off[gw + 1];
    float4 a0 = {0.f, 0.f, 0.f, 0.f};
    float4 a1 = {0.f, 0.f, 0.f, 0.f};
    for (int i = s; i < e; i++) {
        int j = g_src[i];
        float w = g_wgt[i];
        const float4* xr = (const float4*)(g_x + (size_t)j * 256);
        float4 v0 = xr[lane];
        float4 v1 = xr[lane + 32];
        a0.x = fmaf(v0.x, w, a0.x); a0.y = fmaf(v0.y, w, a0.y);
        a0.z = fmaf(v0.z, w, a0.z); a0.w = fmaf(v0.w, w, a0.w);
        a1.x = fmaf(v1.x, w, a1.x); a1.y = fmaf(v1.y, w, a1.y);
        a1.z = fmaf(v1.z, w, a1.z); a1.w = fmaf(v1.w, w, a1.w);
    }
    a0.x = fmaxf(a0.x, 0.f); a0.y = fmaxf(a0.y, 0.f);
    a0.z = fmaxf(a0.z, 0.f); a0.w = fmaxf(a0.w, 0.f);
    a1.x = fmaxf(a1.x, 0.f); a1.y = fmaxf(a1.y, 0.f);
    a1.z = fmaxf(a1.z, 0.f); a1.w = fmaxf(a1.w, 0.f);
    float4* o4 = (float4*)(out + (size_t)gw * 256);
    o4[lane] = a0;
    o4[lane + 32] = a1;
}

// ---------------------------------------------------------------------------
extern "C" void kernel_launch(void* const* d_in, const int* in_sizes, int n_in,
                              void* d_out, int out_size) {
    const float* node_feats = (const float*)d_in[0];
    const float* cond_feats = (const float*)d_in[1];
    const int*   batch_ids  = (const int*)d_in[2];
    const int*   node_j     = (const int*)d_in[3];
    const int*   node_i     = (const int*)d_in[4];
    const float* edge_w     = (const float*)d_in[5];
    const float* edge_p     = (const float*)d_in[6];
    const float* Wc         = (const float*)d_in[7];
    const float* bc         = (const float*)d_in[8];
    const float* Wl         = (const float*)d_in[9];
    float* out = (float*)d_out;

    int N = in_sizes[0] / 256;
    int B = in_sizes[1] / 512;
    int E = in_sizes[3];
    int nblk = (N + 255) / 256;

    static cudaStream_t s2 = nullptr;
    static cudaEvent_t evF = nullptr, evJ = nullptr;
    if (!s2) {
        cudaStreamCreateWithFlags(&s2, cudaStreamNonBlocking);
        cudaEventCreateWithFlags(&evF, cudaEventDisableTiming);
        cudaEventCreateWithFlags(&evJ, cudaEventDisableTiming);
        cudaFuncSetAttribute(gemm_ln_kernel,
                             cudaFuncAttributeMaxDynamicSharedMemorySize, SM_TOTAL);
    }

    // main (legacy) stream: film -> wprep -> gemm -> [join] -> agg
    // side stream s2:       hist -> scan_part -> scan_add -> fill
    film_zero_kernel<<<40, 256>>>(cond_feats, Wc, bc, B, N);
    cudaEventRecord(evF, 0);
    cudaStreamWaitEvent(s2, evF, 0);

    hist_kernel<<<(E + 255) / 256, 256, 0, s2>>>(node_i, E);
    scan_part_kernel<<<nblk, 256, 0, s2>>>(N);
    scan_add_kernel<<<nblk, 256, 0, s2>>>(N, E, nblk);
    fill_kernel<<<(E + 255) / 256, 256, 0, s2>>>(node_i, node_j, edge_w, edge_p, E);
    cudaEventRecord(evJ, s2);

    wprep_kernel<<<dim3(8, 8), dim3(32, 8)>>>(Wl);
    gemm_ln_kernel<<<(N + 63) / 64, 512, SM_TOTAL>>>(node_feats, batch_ids, N);

    cudaStreamWaitEvent(0, evJ, 0);
    agg_kernel<<<(N * 32 + 255) / 256, 256>>>(out, N);
}

// round 10
// speedup vs baseline: 1.1687x; 1.1687x over previous
#include <cuda_runtime.h>
#include <cuda_fp16.h>
#include <cstdint>

// Problem dims (fixed by dataset): N=20000, E=320000, B=16,
// node_dim=256, cond_dim=512, out_dim=256.
#define NMAX 20000
#define EMAX 320000
#define BMAX 16

// Scratch (allocation-free rule: __device__ globals)
__device__ __align__(16) float g_x[(size_t)NMAX * 256];
__device__ __align__(16) float g_gamma[BMAX * 256];
__device__ __align__(16) float g_beta[BMAX * 256];
__device__ __align__(16) __half g_Wf[256 * 256];   // W^T fp16, [n][k]
__device__ int   g_cnt[NMAX];
__device__ int   g_off[NMAX + 1];
__device__ int   g_cur[NMAX];
__device__ int   g_blk[128];
__device__ int   g_src[EMAX];
__device__ float g_wgt[EMAX];

#define SMEM_SWIZZLE_128B(off) ((off) ^ (((off) >> 3) & 0x70))

// warp-level fp16 MMA, fp32 accum (baseline PTX, works on compute_103)
__device__ __forceinline__ void mma16816(float* c, const uint32_t* a,
                                         const uint32_t* b) {
    asm volatile(
        "mma.sync.aligned.m16n8k16.row.col.f32.f16.f16.f32 "
        "{%0,%1,%2,%3},{%4,%5,%6,%7},{%8,%9},{%0,%1,%2,%3};"
        : "+f"(c[0]), "+f"(c[1]), "+f"(c[2]), "+f"(c[3])
        : "r"(a[0]), "r"(a[1]), "r"(a[2]), "r"(a[3]), "r"(b[0]), "r"(b[1]));
}
__device__ __forceinline__ void ldsm_x4(uint32_t* r, uint32_t addr) {
    asm volatile("ldmatrix.sync.aligned.m8n8.x4.shared.b16 {%0,%1,%2,%3}, [%4];"
                 : "=r"(r[0]), "=r"(r[1]), "=r"(r[2]), "=r"(r[3]) : "r"(addr));
}
__device__ __forceinline__ uint32_t smem_to_u32(const void* p) {
    uint32_t a;
    asm("{ .reg .u64 t; cvta.to.shared.u64 t, %1; cvt.u32.u64 %0, t; }"
        : "=r"(a) : "l"(p));
    return a;
}
#define CP_ASYNC16(dst, src) \
    asm volatile("cp.async.cg.shared.global [%0], [%1], 16;" \
                 :: "r"(dst), "l"(src) : "memory")
#define CP_COMMIT() asm volatile("cp.async.commit_group;" ::: "memory")
#define CP_WAIT1() asm volatile("cp.async.wait_group 1;" ::: "memory")
#define CP_WAIT0() asm volatile("cp.async.wait_group 0;" ::: "memory")

// ---------------------------------------------------------------------------
// 0. W prep: transpose W[k][n] fp32 -> g_Wf[n][k] fp16.
// ---------------------------------------------------------------------------
__global__ void wprep_kernel(const float* __restrict__ W) {
    __shared__ float t[32][33];
    int bi = blockIdx.x;           // n-tile
    int bj = blockIdx.y;           // k-tile
    int tx = threadIdx.x, ty = threadIdx.y;   // 32 x 8
#pragma unroll
    for (int i = 0; i < 4; i++)
        t[ty + i * 8][tx] = W[(size_t)(bj * 32 + ty + i * 8) * 256 + bi * 32 + tx];
    __syncthreads();
#pragma unroll
    for (int i = 0; i < 4; i++) {
        int n = bi * 32 + ty + i * 8;
        int k = bj * 32 + tx;
        g_Wf[(size_t)n * 256 + k] = __float2half_rn(t[tx][ty + i * 8]);
    }
}

// ---------------------------------------------------------------------------
// 1. FiLM params + zero CSR counters.
// ---------------------------------------------------------------------------
__global__ void film_zero_kernel(const float* __restrict__ cond,
                                 const float* __restrict__ Wc,
                                 const float* __restrict__ bc, int B, int N) {
    int tid = blockIdx.x * blockDim.x + threadIdx.x;
    for (int i = tid; i < N; i += gridDim.x * blockDim.x) {
        g_cnt[i] = 0; g_cur[i] = 0;
    }
    if (tid >= B * 512) return;
    int b = tid >> 9;
    int o = tid & 511;
    const float* c = cond + b * 512;
    float acc = bc[o];
#pragma unroll 4
    for (int k = 0; k < 512; k++) acc = fmaf(c[k], Wc[k * 512 + o], acc);
    if (o < 256) g_gamma[b * 256 + o] = acc + 1.0f;
    else         g_beta[b * 256 + (o - 256)] = acc;
}

// ---------------------------------------------------------------------------
// 2. hist
// ---------------------------------------------------------------------------
__global__ void hist_kernel(const int* __restrict__ ni, int E) {
    int e = blockIdx.x * blockDim.x + threadIdx.x;
    if (e < E) atomicAdd(&g_cnt[ni[e]], 1);
}

// ---------------------------------------------------------------------------
// 3. Tensor GEMM (mma.sync fp16 2-term split: X = (Ah+Al) @ Wf) + LN/FiLM/ReLU.
//    R8 structure: 256 threads (2m x 4n warps, warp tile 32x64), K chunks of
//    32, cp.async double-buffered W, A register-prefetched + converted.
//    SMEM: W buf0 16K | W buf1 16K | Ah 4K | Al 4K | stats = 41 KB.
// ---------------------------------------------------------------------------
#define SM_W0 0
#define SM_W1 16384
#define SM_AH 32768
#define SM_AL 36864
#define SM_ST 40960
#define SM_TOTAL (40960 + 512)

__device__ __forceinline__ void issue_w_chunk(uint32_t wbuf, int kt, int tid) {
#pragma unroll
    for (int it = 0; it < 4; it++) {
        int item = it * 256 + tid;
        int n = item >> 2;
        int c = item & 3;
        uint32_t off = (uint32_t)((n & 127) * 128 + (n >> 7) * 64 + c * 16);
        uint32_t sw = SMEM_SWIZZLE_128B(off);
        size_t go = (size_t)n * 512 + (size_t)kt * 64 + c * 16;   // bytes
        CP_ASYNC16(wbuf + sw, (const char*)g_Wf + go);
    }
    CP_COMMIT();
}

__global__ void __launch_bounds__(256, 2)
gemm_ln_kernel(const float* __restrict__ A,
               const int* __restrict__ batch_ids, int N) {
    extern __shared__ char sm[];
    uint32_t smb = smem_to_u32(sm);
    float* s_sum = (float*)(sm + SM_ST);        // [64]
    float* s_sq  = (float*)(sm + SM_ST + 256);  // [64]

    int tid = threadIdx.x;
    int wid = tid >> 5, lane = tid & 31;
    int mw = wid >> 2;           // 0..1  m-warp
    int nw = wid & 3;            // 0..3  n-warp
    int m0 = blockIdx.x * 64;

    if (tid < 128) ((float*)(sm + SM_ST))[tid] = 0.0f;

    // ldmatrix per-lane addressing
    int g = lane >> 3;
    int lr = lane & 7;
    uint32_t axor = (uint32_t)(lr << 4);
    uint32_t a_row[2];
#pragma unroll
    for (int tm = 0; tm < 2; tm++)
        a_row[tm] = (uint32_t)((tm * 16 + (g & 1) * 8 + lr) * 128);
    uint32_t a_low_base = (uint32_t)(mw * 64 + (g >> 1) * 16);
    uint32_t b_row[4];
#pragma unroll
    for (int np = 0; np < 4; np++)
        b_row[np] = (uint32_t)((((nw & 1) * 64 + np * 16 + ((g >> 1) & 1) * 8 + lr)) * 128);
    uint32_t b_low_base = (uint32_t)((nw >> 1) * 64 + (g & 1) * 16);

    // A prefetch mapping
    int pm = tid >> 2;
    int prow = m0 + pm;
    const float* aptr = A + (size_t)prow * 256 + (tid & 3) * 8;
    bool pvalid = (prow < N);
    uint32_t a_st_off = SMEM_SWIZZLE_128B(
        (uint32_t)((pm & 31) * 128 + (pm >> 5) * 64 + (tid & 3) * 16));

    float c[2][8][4];
#pragma unroll
    for (int i = 0; i < 2; i++)
#pragma unroll
        for (int j = 0; j < 8; j++)
#pragma unroll
            for (int q = 0; q < 4; q++) c[i][j][q] = 0.0f;

    // ---- prologue
    issue_w_chunk(smb + SM_W0, 0, tid);
    issue_w_chunk(smb + SM_W1, 1, tid);
    float4 aP0 = make_float4(0.f, 0.f, 0.f, 0.f);
    float4 aP1 = make_float4(0.f, 0.f, 0.f, 0.f);
    if (pvalid) {
        aP0 = *(const float4*)(aptr);
        aP1 = *(const float4*)(aptr + 4);
    }

    for (int kt = 0; kt < 8; kt++) {
        if (kt > 0) __syncthreads();
        if (kt >= 1 && kt + 1 < 8)
            issue_w_chunk(smb + SM_W0 + ((kt + 1) & 1) * 16384, kt + 1, tid);

        // store converted A(kt): fp16 hi/lo split
        {
            float f[8] = {aP0.x, aP0.y, aP0.z, aP0.w, aP1.x, aP1.y, aP1.z, aP1.w};
            uint32_t h[4], l[4];
#pragma unroll
            for (int q = 0; q < 4; q++) {
                __half h0 = __float2half_rn(f[2 * q]);
                __half h1 = __float2half_rn(f[2 * q + 1]);
                __half l0 = __float2half_rn(f[2 * q] - __half2float(h0));
                __half l1 = __float2half_rn(f[2 * q + 1] - __half2float(h1));
                h[q] = ((uint32_t)__half_as_ushort(h1) << 16) | __half_as_ushort(h0);
                l[q] = ((uint32_t)__half_as_ushort(l1) << 16) | __half_as_ushort(l0);
            }
            *(uint4*)(sm + SM_AH + a_st_off) = make_uint4(h[0], h[1], h[2], h[3]);
            *(uint4*)(sm + SM_AL + a_st_off) = make_uint4(l[0], l[1], l[2], l[3]);
        }

        if (kt == 7) { CP_WAIT0(); } else { CP_WAIT1(); }
        __syncthreads();

        if (kt + 1 < 8 && pvalid) {
            aP0 = *(const float4*)(aptr + (kt + 1) * 32);
            aP1 = *(const float4*)(aptr + (kt + 1) * 32 + 4);
        }

        uint32_t wb = smb + SM_W0 + (kt & 1) * 16384;
#pragma unroll
        for (int ks = 0; ks < 2; ks++) {
            uint32_t alow = (a_low_base + (uint32_t)(ks * 32)) ^ axor;
            uint32_t blow = (b_low_base + (uint32_t)(ks * 32)) ^ axor;
            uint32_t ah0[4], ah1[4];
            ldsm_x4(ah0, smb + SM_AH + a_row[0] + alow);
            ldsm_x4(ah1, smb + SM_AH + a_row[1] + alow);
            uint32_t bf[4][4];
#pragma unroll
            for (int np = 0; np < 4; np++)
                ldsm_x4(bf[np], wb + b_row[np] + blow);

            // pass 1: ah * W  (16 independent accumulators)
#pragma unroll
            for (int np = 0; np < 4; np++) {
                mma16816(c[0][2 * np],     ah0, bf[np]);
                mma16816(c[0][2 * np + 1], ah0, bf[np] + 2);
                mma16816(c[1][2 * np],     ah1, bf[np]);
                mma16816(c[1][2 * np + 1], ah1, bf[np] + 2);
            }
            // pass 2: al * W
            {
                uint32_t al0[4], al1[4];
                ldsm_x4(al0, smb + SM_AL + a_row[0] + alow);
                ldsm_x4(al1, smb + SM_AL + a_row[1] + alow);
#pragma unroll
                for (int np = 0; np < 4; np++) {
                    mma16816(c[0][2 * np],     al0, bf[np]);
                    mma16816(c[0][2 * np + 1], al0, bf[np] + 2);
                    mma16816(c[1][2 * np],     al1, bf[np]);
                    mma16816(c[1][2 * np + 1], al1, bf[np] + 2);
                }
            }
        }
    }

    // ---- LN stats: quad-shuffle partials, smem atomics across n-warps ----
#pragma unroll
    for (int tm = 0; tm < 2; tm++) {
#pragma unroll
        for (int h = 0; h < 2; h++) {
            int rl = mw * 32 + tm * 16 + h * 8 + (lane >> 2);
            float ps = 0.f, pq = 0.f;
#pragma unroll
            for (int nt = 0; nt < 8; nt++) {
                float v0 = c[tm][nt][2 * h], v1 = c[tm][nt][2 * h + 1];
                ps += v0 + v1;
                pq = fmaf(v0, v0, fmaf(v1, v1, pq));
            }
            ps += __shfl_xor_sync(0xffffffffu, ps, 1);
            pq += __shfl_xor_sync(0xffffffffu, pq, 1);
            ps += __shfl_xor_sync(0xffffffffu, ps, 2);
            pq += __shfl_xor_sync(0xffffffffu, pq, 2);
            if ((lane & 3) == 0) {
                atomicAdd(&s_sum[rl], ps);
                atomicAdd(&s_sq[rl], pq);
            }
        }
    }
    __syncthreads();

    // ---- normalize + FiLM + ReLU from fragments -> g_x ----
#pragma unroll
    for (int tm = 0; tm < 2; tm++) {
#pragma unroll
        for (int h = 0; h < 2; h++) {
            int rl = mw * 32 + tm * 16 + h * 8 + (lane >> 2);
            int row = m0 + rl;
            if (row >= N) continue;
            float mu = s_sum[rl] * (1.0f / 256.0f);
            float var = fmaxf(s_sq[rl] * (1.0f / 256.0f) - mu * mu, 0.0f);
            float rs = rsqrtf(var + 1e-5f);
            int b = batch_ids[row];
            const float* gg = g_gamma + b * 256;
            const float* bb = g_beta + b * 256;
            float* xo = g_x + (size_t)row * 256;
#pragma unroll
            for (int nt = 0; nt < 8; nt++) {
                int col = nw * 64 + nt * 8 + (lane & 3) * 2;
                float2 gv = *(const float2*)(gg + col);
                float2 ev = *(const float2*)(bb + col);
                float2 o;
                o.x = fmaxf(fmaf((c[tm][nt][2 * h] - mu) * rs, gv.x, ev.x), 0.f);
                o.y = fmaxf(fmaf((c[tm][nt][2 * h + 1] - mu) * rs, gv.y, ev.y), 0.f);
                *(float2*)(xo + col) = o;
            }
        }
    }
}

// ---------------------------------------------------------------------------
// scan_part / scan_add / fill / agg (unchanged)
// ---------------------------------------------------------------------------
__global__ void scan_part_kernel(int N) {
    __shared__ int wsum[8];
    int idx = blockIdx.x * 256 + threadIdx.x;
    int lane = threadIdx.x & 31;
    int wid = threadIdx.x >> 5;
    int v = (idx < N) ? g_cnt[idx] : 0;
    int s = v;
#pragma unroll
    for (int o = 1; o < 32; o <<= 1) {
        int t = __shfl_up_sync(0xffffffffu, s, o);
        if (lane >= o) s += t;
    }
    if (lane == 31) wsum[wid] = s;
    __syncthreads();
    if (wid == 0) {
        int ws = (lane < 8) ? wsum[lane] : 0;
#pragma unroll
        for (int o = 1; o < 8; o <<= 1) {
            int t = __shfl_up_sync(0xffffffffu, ws, o);
            if (lane >= o) ws += t;
        }
        if (lane < 8) wsum[lane] = ws;
    }
    __syncthreads();
    int excl = s - v + (wid ? wsum[wid - 1] : 0);
    if (idx < N) g_off[idx] = excl;
    if (threadIdx.x == 255) g_blk[blockIdx.x] = excl + v;
}

__global__ void scan_add_kernel(int N, int E, int nblk) {
    __shared__ int prefix;
    int bid = blockIdx.x;
    if (threadIdx.x < 32) {
        int acc = 0;
        for (int t = threadIdx.x; t < bid; t += 32) acc += g_blk[t];
#pragma unroll
        for (int o = 16; o; o >>= 1) acc += __shfl_xor_sync(0xffffffffu, acc, o);
        if (threadIdx.x == 0) prefix = acc;
    }
    __syncthreads();
    int idx = bid * 256 + threadIdx.x;
    if (idx < N && bid > 0) g_off[idx] += prefix;
    if (idx == 0) g_off[N] = E;
}

__global__ void fill_kernel(const int* __restrict__ ni,
                            const int* __restrict__ nj,
                            const float* __restrict__ ew,
                            const float* __restrict__ ep, int E) {
    int e = blockIdx.x * blockDim.x + threadIdx.x;
    if (e < E) {
        int dst = ni[e];
        int p = atomicAdd(&g_cur[dst], 1);
        int pos = g_off[dst] + p;
        g_src[pos] = nj[e];
        g_wgt[pos] = ew[e] * ep[e];
    }
}

__global__ void agg_kernel(float* __restrict__ out, int N) {
    int gw = (blockIdx.x * blockDim.x + threadIdx.x) >> 5;
    int lane = threadIdx.x & 31;
    if (gw >= N) return;
    int s = g_off[gw];
    int e = g_off[gw + 1];
    float4 a0 = {0.f, 0.f, 0.f, 0.f};
    float4 a1 = {0.f, 0.f, 0.f, 0.f};
    for (int i = s; i < e; i++) {
        int j = g_src[i];
        float w = g_wgt[i];
        const float4* xr = (const float4*)(g_x + (size_t)j * 256);
        float4 v0 = xr[lane];
        float4 v1 = xr[lane + 32];
        a0.x = fmaf(v0.x, w, a0.x); a0.y = fmaf(v0.y, w, a0.y);
        a0.z = fmaf(v0.z, w, a0.z); a0.w = fmaf(v0.w, w, a0.w);
        a1.x = fmaf(v1.x, w, a1.x); a1.y = fmaf(v1.y, w, a1.y);
        a1.z = fmaf(v1.z, w, a1.z); a1.w = fmaf(v1.w, w, a1.w);
    }
    a0.x = fmaxf(a0.x, 0.f); a0.y = fmaxf(a0.y, 0.f);
    a0.z = fmaxf(a0.z, 0.f); a0.w = fmaxf(a0.w, 0.f);
    a1.x = fmaxf(a1.x, 0.f); a1.y = fmaxf(a1.y, 0.f);
    a1.z = fmaxf(a1.z, 0.f); a1.w = fmaxf(a1.w, 0.f);
    float4* o4 = (float4*)(out + (size_t)gw * 256);
    o4[lane] = a0;
    o4[lane + 32] = a1;
}

// ---------------------------------------------------------------------------
extern "C" void kernel_launch(void* const* d_in, const int* in_sizes, int n_in,
                              void* d_out, int out_size) {
    const float* node_feats = (const float*)d_in[0];
    const float* cond_feats = (const float*)d_in[1];
    const int*   batch_ids  = (const int*)d_in[2];
    const int*   node_j     = (const int*)d_in[3];
    const int*   node_i     = (const int*)d_in[4];
    const float* edge_w     = (const float*)d_in[5];
    const float* edge_p     = (const float*)d_in[6];
    const float* Wc         = (const float*)d_in[7];
    const float* bc         = (const float*)d_in[8];
    const float* Wl         = (const float*)d_in[9];
    float* out = (float*)d_out;

    int N = in_sizes[0] / 256;
    int B = in_sizes[1] / 512;
    int E = in_sizes[3];
    int nblk = (N + 255) / 256;

    static cudaStream_t s2 = nullptr;
    static cudaEvent_t evF = nullptr, evJ = nullptr;
    if (!s2) {
        cudaStreamCreateWithFlags(&s2, cudaStreamNonBlocking);
        cudaEventCreateWithFlags(&evF, cudaEventDisableTiming);
        cudaEventCreateWithFlags(&evJ, cudaEventDisableTiming);
        cudaFuncSetAttribute(gemm_ln_kernel,
                             cudaFuncAttributeMaxDynamicSharedMemorySize, SM_TOTAL);
    }

    // main (legacy) stream: wprep -> film -> gemm -> [join] -> agg
    // side stream s2:       hist -> scan_part -> scan_add -> fill
    wprep_kernel<<<dim3(8, 8), dim3(32, 8)>>>(Wl);
    film_zero_kernel<<<40, 256>>>(cond_feats, Wc, bc, B, N);
    cudaEventRecord(evF, 0);
    cudaStreamWaitEvent(s2, evF, 0);

    hist_kernel<<<(E + 255) / 256, 256, 0, s2>>>(node_i, E);
    scan_part_kernel<<<nblk, 256, 0, s2>>>(N);
    scan_add_kernel<<<nblk, 256, 0, s2>>>(N, E, nblk);
    fill_kernel<<<(E + 255) / 256, 256, 0, s2>>>(node_i, node_j, edge_w, edge_p, E);
    cudaEventRecord(evJ, s2);

    gemm_ln_kernel<<<(N + 63) / 64, 256, SM_TOTAL>>>(node_feats, batch_ids, N);

    cudaStreamWaitEvent(0, evJ, 0);
    agg_kernel<<<(N * 32 + 255) / 256, 256>>>(out, N);
}

// round 11
// speedup vs baseline: 1.4878x; 1.2730x over previous
#include <cuda_runtime.h>
#include <cuda_fp16.h>
#include <cstdint>

// Problem dims (fixed by dataset): N=20000, E=320000, B=16,
// node_dim=256, cond_dim=512, out_dim=256.
#define NMAX 20000
#define EMAX 320000
#define BMAX 16

// Scratch (allocation-free rule: __device__ globals)
__device__ __align__(16) __half g_xh[(size_t)NMAX * 256];  // post-LN x, fp16
__device__ __align__(16) float g_gamma[BMAX * 256];
__device__ __align__(16) float g_beta[BMAX * 256];
__device__ __align__(16) __half g_Wf[256 * 256];   // W^T fp16, [n][k]
__device__ int   g_cnt[NMAX];
__device__ int   g_off[NMAX + 1];
__device__ int   g_cur[NMAX];
__device__ int   g_blk[128];
__device__ int   g_src[EMAX];
__device__ float g_wgt[EMAX];

#define SMEM_SWIZZLE_128B(off) ((off) ^ (((off) >> 3) & 0x70))

// warp-level fp16 MMA, fp32 accum (baseline PTX, works on compute_103)
__device__ __forceinline__ void mma16816(float* c, const uint32_t* a,
                                         const uint32_t* b) {
    asm volatile(
        "mma.sync.aligned.m16n8k16.row.col.f32.f16.f16.f32 "
        "{%0,%1,%2,%3},{%4,%5,%6,%7},{%8,%9},{%0,%1,%2,%3};"
        : "+f"(c[0]), "+f"(c[1]), "+f"(c[2]), "+f"(c[3])
        : "r"(a[0]), "r"(a[1]), "r"(a[2]), "r"(a[3]), "r"(b[0]), "r"(b[1]));
}
__device__ __forceinline__ void ldsm_x4(uint32_t* r, uint32_t addr) {
    asm volatile("ldmatrix.sync.aligned.m8n8.x4.shared.b16 {%0,%1,%2,%3}, [%4];"
                 : "=r"(r[0]), "=r"(r[1]), "=r"(r[2]), "=r"(r[3]) : "r"(addr));
}
__device__ __forceinline__ uint32_t smem_to_u32(const void* p) {
    uint32_t a;
    asm("{ .reg .u64 t; cvta.to.shared.u64 t, %1; cvt.u32.u64 %0, t; }"
        : "=r"(a) : "l"(p));
    return a;
}
#define CP_ASYNC16(dst, src) \
    asm volatile("cp.async.cg.shared.global [%0], [%1], 16;" \
                 :: "r"(dst), "l"(src) : "memory")
#define CP_COMMIT() asm volatile("cp.async.commit_group;" ::: "memory")
#define CP_WAIT1() asm volatile("cp.async.wait_group 1;" ::: "memory")
#define CP_WAIT0() asm volatile("cp.async.wait_group 0;" ::: "memory")

// ---------------------------------------------------------------------------
// 0. W prep: transpose W[k][n] fp32 -> g_Wf[n][k] fp16.
// ---------------------------------------------------------------------------
__global__ void wprep_kernel(const float* __restrict__ W) {
    __shared__ float t[32][33];
    int bi = blockIdx.x;           // n-tile
    int bj = blockIdx.y;           // k-tile
    int tx = threadIdx.x, ty = threadIdx.y;   // 32 x 8
#pragma unroll
    for (int i = 0; i < 4; i++)
        t[ty + i * 8][tx] = W[(size_t)(bj * 32 + ty + i * 8) * 256 + bi * 32 + tx];
    __syncthreads();
#pragma unroll
    for (int i = 0; i < 4; i++) {
        int n = bi * 32 + ty + i * 8;
        int k = bj * 32 + tx;
        g_Wf[(size_t)n * 256 + k] = __float2half_rn(t[tx][ty + i * 8]);
    }
}

// ---------------------------------------------------------------------------
// 1. FiLM params + zero CSR counters.
// ---------------------------------------------------------------------------
__global__ void film_zero_kernel(const float* __restrict__ cond,
                                 const float* __restrict__ Wc,
                                 const float* __restrict__ bc, int B, int N) {
    int tid = blockIdx.x * blockDim.x + threadIdx.x;
    for (int i = tid; i < N; i += gridDim.x * blockDim.x) {
        g_cnt[i] = 0; g_cur[i] = 0;
    }
    if (tid >= B * 512) return;
    int b = tid >> 9;
    int o = tid & 511;
    const float* c = cond + b * 512;
    float acc = bc[o];
#pragma unroll 4
    for (int k = 0; k < 512; k++) acc = fmaf(c[k], Wc[k * 512 + o], acc);
    if (o < 256) g_gamma[b * 256 + o] = acc + 1.0f;
    else         g_beta[b * 256 + (o - 256)] = acc;
}

// ---------------------------------------------------------------------------
// 2. hist
// ---------------------------------------------------------------------------
__global__ void hist_kernel(const int* __restrict__ ni, int E) {
    int e = blockIdx.x * blockDim.x + threadIdx.x;
    if (e < E) atomicAdd(&g_cnt[ni[e]], 1);
}

// ---------------------------------------------------------------------------
// 3. Tensor GEMM (mma.sync fp16, single pass: X = Af @ Wf) + LN/FiLM/ReLU.
//    256 threads (2m x 4n warps, warp tile 32x64), K chunks of 32,
//    cp.async double-buffered W, A register-prefetched + converted.
//    SMEM: W buf0 16K | W buf1 16K | Ah 4K | stats = 37 KB.
// ---------------------------------------------------------------------------
#define SM_W0 0
#define SM_W1 16384
#define SM_AH 32768
#define SM_ST 36864
#define SM_TOTAL (36864 + 512)

__device__ __forceinline__ void issue_w_chunk(uint32_t wbuf, int kt, int tid) {
#pragma unroll
    for (int it = 0; it < 4; it++) {
        int item = it * 256 + tid;
        int n = item >> 2;
        int c = item & 3;
        uint32_t off = (uint32_t)((n & 127) * 128 + (n >> 7) * 64 + c * 16);
        uint32_t sw = SMEM_SWIZZLE_128B(off);
        size_t go = (size_t)n * 512 + (size_t)kt * 64 + c * 16;   // bytes
        CP_ASYNC16(wbuf + sw, (const char*)g_Wf + go);
    }
    CP_COMMIT();
}

__global__ void __launch_bounds__(256, 2)
gemm_ln_kernel(const float* __restrict__ A,
               const int* __restrict__ batch_ids, int N) {
    extern __shared__ char sm[];
    uint32_t smb = smem_to_u32(sm);
    float* s_sum = (float*)(sm + SM_ST);        // [64]
    float* s_sq  = (float*)(sm + SM_ST + 256);  // [64]

    int tid = threadIdx.x;
    int wid = tid >> 5, lane = tid & 31;
    int mw = wid >> 2;           // 0..1  m-warp
    int nw = wid & 3;            // 0..3  n-warp
    int m0 = blockIdx.x * 64;

    if (tid < 128) ((float*)(sm + SM_ST))[tid] = 0.0f;

    // ldmatrix per-lane addressing
    int g = lane >> 3;
    int lr = lane & 7;
    uint32_t axor = (uint32_t)(lr << 4);
    uint32_t a_row[2];
#pragma unroll
    for (int tm = 0; tm < 2; tm++)
        a_row[tm] = (uint32_t)((tm * 16 + (g & 1) * 8 + lr) * 128);
    uint32_t a_low_base = (uint32_t)(mw * 64 + (g >> 1) * 16);
    uint32_t b_row[4];
#pragma unroll
    for (int np = 0; np < 4; np++)
        b_row[np] = (uint32_t)((((nw & 1) * 64 + np * 16 + ((g >> 1) & 1) * 8 + lr)) * 128);
    uint32_t b_low_base = (uint32_t)((nw >> 1) * 64 + (g & 1) * 16);

    // A prefetch mapping
    int pm = tid >> 2;
    int prow = m0 + pm;
    const float* aptr = A + (size_t)prow * 256 + (tid & 3) * 8;
    bool pvalid = (prow < N);
    uint32_t a_st_off = SMEM_SWIZZLE_128B(
        (uint32_t)((pm & 31) * 128 + (pm >> 5) * 64 + (tid & 3) * 16));

    float c[2][8][4];
#pragma unroll
    for (int i = 0; i < 2; i++)
#pragma unroll
        for (int j = 0; j < 8; j++)
#pragma unroll
            for (int q = 0; q < 4; q++) c[i][j][q] = 0.0f;

    // ---- prologue
    issue_w_chunk(smb + SM_W0, 0, tid);
    issue_w_chunk(smb + SM_W1, 1, tid);
    float4 aP0 = make_float4(0.f, 0.f, 0.f, 0.f);
    float4 aP1 = make_float4(0.f, 0.f, 0.f, 0.f);
    if (pvalid) {
        aP0 = *(const float4*)(aptr);
        aP1 = *(const float4*)(aptr + 4);
    }

    for (int kt = 0; kt < 8; kt++) {
        if (kt > 0) __syncthreads();
        if (kt >= 1 && kt + 1 < 8)
            issue_w_chunk(smb + SM_W0 + ((kt + 1) & 1) * 16384, kt + 1, tid);

        // store converted A(kt) fp16
        {
            float f[8] = {aP0.x, aP0.y, aP0.z, aP0.w, aP1.x, aP1.y, aP1.z, aP1.w};
            uint32_t h[4];
#pragma unroll
            for (int q = 0; q < 4; q++) {
                __half h0 = __float2half_rn(f[2 * q]);
                __half h1 = __float2half_rn(f[2 * q + 1]);
                h[q] = ((uint32_t)__half_as_ushort(h1) << 16) | __half_as_ushort(h0);
            }
            *(uint4*)(sm + SM_AH + a_st_off) = make_uint4(h[0], h[1], h[2], h[3]);
        }

        if (kt == 7) { CP_WAIT0(); } else { CP_WAIT1(); }
        __syncthreads();

        if (kt + 1 < 8 && pvalid) {
            aP0 = *(const float4*)(aptr + (kt + 1) * 32);
            aP1 = *(const float4*)(aptr + (kt + 1) * 32 + 4);
        }

        uint32_t wb = smb + SM_W0 + (kt & 1) * 16384;
#pragma unroll
        for (int ks = 0; ks < 2; ks++) {
            uint32_t alow = (a_low_base + (uint32_t)(ks * 32)) ^ axor;
            uint32_t blow = (b_low_base + (uint32_t)(ks * 32)) ^ axor;
            uint32_t ah0[4], ah1[4];
            ldsm_x4(ah0, smb + SM_AH + a_row[0] + alow);
            ldsm_x4(ah1, smb + SM_AH + a_row[1] + alow);
            uint32_t bf[4][4];
#pragma unroll
            for (int np = 0; np < 4; np++)
                ldsm_x4(bf[np], wb + b_row[np] + blow);

            // 16 independent accumulators per warp
#pragma unroll
            for (int np = 0; np < 4; np++) {
                mma16816(c[0][2 * np],     ah0, bf[np]);
                mma16816(c[0][2 * np + 1], ah0, bf[np] + 2);
                mma16816(c[1][2 * np],     ah1, bf[np]);
                mma16816(c[1][2 * np + 1], ah1, bf[np] + 2);
            }
        }
    }

    // ---- LN stats: quad-shuffle partials, smem atomics across n-warps ----
#pragma unroll
    for (int tm = 0; tm < 2; tm++) {
#pragma unroll
        for (int h = 0; h < 2; h++) {
            int rl = mw * 32 + tm * 16 + h * 8 + (lane >> 2);
            float ps = 0.f, pq = 0.f;
#pragma unroll
            for (int nt = 0; nt < 8; nt++) {
                float v0 = c[tm][nt][2 * h], v1 = c[tm][nt][2 * h + 1];
                ps += v0 + v1;
                pq = fmaf(v0, v0, fmaf(v1, v1, pq));
            }
            ps += __shfl_xor_sync(0xffffffffu, ps, 1);
            pq += __shfl_xor_sync(0xffffffffu, pq, 1);
            ps += __shfl_xor_sync(0xffffffffu, ps, 2);
            pq += __shfl_xor_sync(0xffffffffu, pq, 2);
            if ((lane & 3) == 0) {
                atomicAdd(&s_sum[rl], ps);
                atomicAdd(&s_sq[rl], pq);
            }
        }
    }
    __syncthreads();

    // ---- normalize + FiLM + ReLU from fragments -> g_xh (fp16) ----
#pragma unroll
    for (int tm = 0; tm < 2; tm++) {
#pragma unroll
        for (int h = 0; h < 2; h++) {
            int rl = mw * 32 + tm * 16 + h * 8 + (lane >> 2);
            int row = m0 + rl;
            if (row >= N) continue;
            float mu = s_sum[rl] * (1.0f / 256.0f);
            float var = fmaxf(s_sq[rl] * (1.0f / 256.0f) - mu * mu, 0.0f);
            float rs = rsqrtf(var + 1e-5f);
            int b = batch_ids[row];
            const float* gg = g_gamma + b * 256;
            const float* bb = g_beta + b * 256;
            __half2* xo = (__half2*)(g_xh + (size_t)row * 256);
#pragma unroll
            for (int nt = 0; nt < 8; nt++) {
                int col = nw * 64 + nt * 8 + (lane & 3) * 2;
                float2 gv = *(const float2*)(gg + col);
                float2 ev = *(const float2*)(bb + col);
                float2 o;
                o.x = fmaxf(fmaf((c[tm][nt][2 * h] - mu) * rs, gv.x, ev.x), 0.f);
                o.y = fmaxf(fmaf((c[tm][nt][2 * h + 1] - mu) * rs, gv.y, ev.y), 0.f);
                xo[col >> 1] = __float22half2_rn(o);
            }
        }
    }
}

// ---------------------------------------------------------------------------
// scan_part / scan_add / fill
// ---------------------------------------------------------------------------
__global__ void scan_part_kernel(int N) {
    __shared__ int wsum[8];
    int idx = blockIdx.x * 256 + threadIdx.x;
    int lane = threadIdx.x & 31;
    int wid = threadIdx.x >> 5;
    int v = (idx < N) ? g_cnt[idx] : 0;
    int s = v;
#pragma unroll
    for (int o = 1; o < 32; o <<= 1) {
        int t = __shfl_up_sync(0xffffffffu, s, o);
        if (lane >= o) s += t;
    }
    if (lane == 31) wsum[wid] = s;
    __syncthreads();
    if (wid == 0) {
        int ws = (lane < 8) ? wsum[lane] : 0;
#pragma unroll
        for (int o = 1; o < 8; o <<= 1) {
            int t = __shfl_up_sync(0xffffffffu, ws, o);
            if (lane >= o) ws += t;
        }
        if (lane < 8) wsum[lane] = ws;
    }
    __syncthreads();
    int excl = s - v + (wid ? wsum[wid - 1] : 0);
    if (idx < N) g_off[idx] = excl;
    if (threadIdx.x == 255) g_blk[blockIdx.x] = excl + v;
}

__global__ void scan_add_kernel(int N, int E, int nblk) {
    __shared__ int prefix;
    int bid = blockIdx.x;
    if (threadIdx.x < 32) {
        int acc = 0;
        for (int t = threadIdx.x; t < bid; t += 32) acc += g_blk[t];
#pragma unroll
        for (int o = 16; o; o >>= 1) acc += __shfl_xor_sync(0xffffffffu, acc, o);
        if (threadIdx.x == 0) prefix = acc;
    }
    __syncthreads();
    int idx = bid * 256 + threadIdx.x;
    if (idx < N && bid > 0) g_off[idx] += prefix;
    if (idx == 0) g_off[N] = E;
}

__global__ void fill_kernel(const int* __restrict__ ni,
                            const int* __restrict__ nj,
                            const float* __restrict__ ew,
                            const float* __restrict__ ep, int E) {
    int e = blockIdx.x * blockDim.x + threadIdx.x;
    if (e < E) {
        int dst = ni[e];
        int p = atomicAdd(&g_cur[dst], 1);
        int pos = g_off[dst] + p;
        g_src[pos] = nj[e];
        g_wgt[pos] = ew[e] * ep[e];
    }
}

// ---------------------------------------------------------------------------
// 4. Pull aggregation from fp16 x: warp per node; lane owns 8 cols (16B/row).
// ---------------------------------------------------------------------------
__global__ void agg_kernel(float* __restrict__ out, int N) {
    int gw = (blockIdx.x * blockDim.x + threadIdx.x) >> 5;
    int lane = threadIdx.x & 31;
    if (gw >= N) return;
    int s = g_off[gw];
    int e = g_off[gw + 1];
    float acc[8] = {0.f, 0.f, 0.f, 0.f, 0.f, 0.f, 0.f, 0.f};
    for (int i = s; i < e; i++) {
        int j = g_src[i];
        float w = g_wgt[i];
        uint4 v = *(const uint4*)((const char*)g_xh + (size_t)j * 512 + lane * 16);
        const __half2* hv = (const __half2*)&v;
#pragma unroll
        for (int q = 0; q < 4; q++) {
            float2 f = __half22float2(hv[q]);
            acc[2 * q]     = fmaf(f.x, w, acc[2 * q]);
            acc[2 * q + 1] = fmaf(f.y, w, acc[2 * q + 1]);
        }
    }
    float4 o0, o1;
    o0.x = fmaxf(acc[0], 0.f); o0.y = fmaxf(acc[1], 0.f);
    o0.z = fmaxf(acc[2], 0.f); o0.w = fmaxf(acc[3], 0.f);
    o1.x = fmaxf(acc[4], 0.f); o1.y = fmaxf(acc[5], 0.f);
    o1.z = fmaxf(acc[6], 0.f); o1.w = fmaxf(acc[7], 0.f);
    float4* o4 = (float4*)(out + (size_t)gw * 256 + lane * 8);
    o4[0] = o0;
    o4[1] = o1;
}

// ---------------------------------------------------------------------------
extern "C" void kernel_launch(void* const* d_in, const int* in_sizes, int n_in,
                              void* d_out, int out_size) {
    const float* node_feats = (const float*)d_in[0];
    const float* cond_feats = (const float*)d_in[1];
    const int*   batch_ids  = (const int*)d_in[2];
    const int*   node_j     = (const int*)d_in[3];
    const int*   node_i     = (const int*)d_in[4];
    const float* edge_w     = (const float*)d_in[5];
    const float* edge_p     = (const float*)d_in[6];
    const float* Wc         = (const float*)d_in[7];
    const float* bc         = (const float*)d_in[8];
    const float* Wl         = (const float*)d_in[9];
    float* out = (float*)d_out;

    int N = in_sizes[0] / 256;
    int B = in_sizes[1] / 512;
    int E = in_sizes[3];
    int nblk = (N + 255) / 256;

    static cudaStream_t s2 = nullptr;
    static cudaEvent_t evF = nullptr, evJ = nullptr;
    if (!s2) {
        cudaStreamCreateWithFlags(&s2, cudaStreamNonBlocking);
        cudaEventCreateWithFlags(&evF, cudaEventDisableTiming);
        cudaEventCreateWithFlags(&evJ, cudaEventDisableTiming);
        cudaFuncSetAttribute(gemm_ln_kernel,
                             cudaFuncAttributeMaxDynamicSharedMemorySize, SM_TOTAL);
    }

    // main (legacy) stream: wprep -> film -> gemm -> [join] -> agg
    // side stream s2:       hist -> scan_part -> scan_add -> fill
    wprep_kernel<<<dim3(8, 8), dim3(32, 8)>>>(Wl);
    film_zero_kernel<<<40, 256>>>(cond_feats, Wc, bc, B, N);
    cudaEventRecord(evF, 0);
    cudaStreamWaitEvent(s2, evF, 0);

    hist_kernel<<<(E + 255) / 256, 256, 0, s2>>>(node_i, E);
    scan_part_kernel<<<nblk, 256, 0, s2>>>(N);
    scan_add_kernel<<<nblk, 256, 0, s2>>>(N, E, nblk);
    fill_kernel<<<(E + 255) / 256, 256, 0, s2>>>(node_i, node_j, edge_w, edge_p, E);
    cudaEventRecord(evJ, s2);

    gemm_ln_kernel<<<(N + 63) / 64, 256, SM_TOTAL>>>(node_feats, batch_ids, N);

    cudaStreamWaitEvent(0, evJ, 0);
    agg_kernel<<<(N * 32 + 255) / 256, 256>>>(out, N);
}